// round 16
// baseline (speedup 1.0000x reference)
#include <cuda_runtime.h>
#include <cuda_fp16.h>
#include <cstdint>

// Problem constants (fixed shapes for Chowder_17188459119037)
#define BB     16
#define NN     8000
#define DD     2048
#define HH     128
#define MROWS  (BB * NN)        // 128000
#define NTOP   100
#define NBOT   100
#define NEXT   (NTOP + NBOT)    // 200

#define TM      128             // rows per CTA (R11 optimum)
#define NIT     (DD / 32)       // 64 k32 iterations
#define AW      20              // A smem row stride in uints (40 halfs)
#define SEGS    8
#define SEGLEN  (NN / SEGS)     // 1000

__device__ float g_scores[MROWS];
// W1 packed fp16 fragment order: [k16tile][ntile][lane] -> uint2
__device__ __align__(16) unsigned g_W1H[(DD / 16) * 16 * 32 * 2];
__device__ float g_ctop[BB * SEGS * NTOP];
__device__ float g_cbot[BB * SEGS * NBOT];
__device__ int   g_mask_mode;   // 0=int32, 1=uint8, 2=float32

__device__ __forceinline__ float neg_inf() { return __int_as_float(0xff800000); }
__device__ __forceinline__ float pos_inf() { return __int_as_float(0x7f800000); }
__device__ __forceinline__ float sigmoidf_fast(float x) {
    return 1.0f / (1.0f + __expf(-x));
}
__device__ __forceinline__ bool read_mask(const void* mask, size_t r, int mode) {
    if (mode == 1) return ((const unsigned char*)mask)[r] != 0;
    if (mode == 0) return ((const int*)mask)[r] != 0;
    return ((const float*)mask)[r] != 0.0f;
}
__device__ __forceinline__ uint32_t smem_u32(const void* p) {
    uint32_t a;
    asm("{ .reg .u64 t; cvta.to.shared.u64 t, %1; cvt.u32.u64 %0, t; }"
        : "=r"(a) : "l"(p));
    return a;
}
__device__ __forceinline__ uint32_t f16x2(float lo, float hi) {
    uint32_t r;
    asm("cvt.rn.f16x2.f32 %0, %1, %2;" : "=r"(r) : "f"(hi), "f"(lo));
    return r;
}
// streaming (evict-first) float4 load — keeps A out of L1 LRU, protecting B
__device__ __forceinline__ float4 ldcs4(const float4* p) {
    float4 v;
    asm volatile("ld.global.cs.v4.f32 {%0,%1,%2,%3}, [%4];"
                 : "=f"(v.x), "=f"(v.y), "=f"(v.z), "=f"(v.w) : "l"(p));
    return v;
}
__device__ __forceinline__ void mma16(float* d, const uint32_t* a,
                                      uint32_t b0, uint32_t b1) {
    asm volatile(
        "mma.sync.aligned.m16n8k16.row.col.f32.f16.f16.f32 "
        "{%0,%1,%2,%3}, {%4,%5,%6,%7}, {%8,%9}, {%0,%1,%2,%3};"
        : "+f"(d[0]), "+f"(d[1]), "+f"(d[2]), "+f"(d[3])
        : "r"(a[0]), "r"(a[1]), "r"(a[2]), "r"(a[3]), "r"(b0), "r"(b1));
}
__device__ __forceinline__ void ldmatrix4(uint32_t* a, uint32_t saddr) {
    asm volatile(
        "ldmatrix.sync.aligned.m8n8.x4.shared.b16 {%0,%1,%2,%3}, [%4];"
        : "=r"(a[0]), "=r"(a[1]), "=r"(a[2]), "=r"(a[3]) : "r"(saddr));
}

// ============================================================================
// Kernel 0 (fused): blocks 0..255 pack W1 -> g_W1H; block 256 detects mask dtype
// ============================================================================
__global__ void prep_kernel(const float* __restrict__ W1,
                            const unsigned* __restrict__ m) {
    if (blockIdx.x == 256) {
        __shared__ int s_f32, s_u8;
        if (threadIdx.x == 0) { s_f32 = 0; s_u8 = 0; }
        __syncthreads();
        int f32 = 0, u8 = 0;
        for (int i = threadIdx.x; i < 8000; i += 256) {
            unsigned v = m[i];
            if (v == 0x3F800000u) f32 = 1;
            else if (v > 1u)      u8 = 1;
        }
        if (f32) s_f32 = 1;
        if (u8)  s_u8 = 1;
        __syncthreads();
        if (threadIdx.x == 0) g_mask_mode = s_f32 ? 2 : (s_u8 ? 1 : 0);
        return;
    }
    int i = blockIdx.x * 256 + threadIdx.x;   // 0..65535
    int lane = i & 31, nt = (i >> 5) & 15, tile = i >> 9;
    int n = nt * 8 + (lane >> 2);
    int k = tile * 16 + 2 * (lane & 3);
    uint32_t r0 = f16x2(W1[(size_t)k * HH + n],       W1[(size_t)(k + 1) * HH + n]);
    uint32_t r1 = f16x2(W1[(size_t)(k + 8) * HH + n], W1[(size_t)(k + 9) * HH + n]);
    ((uint2*)g_W1H)[i] = make_uint2(r0, r1);
}

// ============================================================================
// Kernel 1: fp16 mma GEMM (fp32 accum). CTA = 128x128, 256 thr, 2M x 4N.
// R15 configuration (L1-traffic optimum + streaming A loads). UNCHANGED.
// ============================================================================
__global__ __launch_bounds__(256, 2) void score_kernel(
    const float* __restrict__ F,
    const float* __restrict__ b1,
    const float* __restrict__ W2,
    const float* __restrict__ b2,
    const void*  __restrict__ mask)
{
    __shared__ unsigned Ah[2][TM * AW];    // 2 x 10 KB (fp16, stride 40 halfs)
    __shared__ float    part[4][TM];       // 2 KB

    const int tid  = threadIdx.x;
    const int lane = tid & 31;
    const int wid  = tid >> 5;
    const int nw   = wid & 3;     // 4 N-warps x 32 cols
    const int mw   = wid >> 2;    // 2 M-warps x 64 rows
    const int q    = lane & 3;
    const int lr   = lane >> 2;
    const size_t row_base = (size_t)blockIdx.x * TM;

    const int lm_row = mw * 64 + (lane & 15);
    const int lm_off = (lane >> 4) * 4;

    const int arow = tid >> 1;
    const int ah   = tid & 1;
    const float* Abase = F + (row_base + arow) * DD + ah * 16;

    const uint2* Bg = (const uint2*)g_W1H + (nw * 4) * 32 + lane;

    float acc[4][4][4];
#pragma unroll
    for (int mt = 0; mt < 4; mt++)
#pragma unroll
        for (int nf = 0; nf < 4; nf++)
#pragma unroll
            for (int e = 0; e < 4; e++) acc[mt][nf][e] = 0.f;

    float4 av[4];
#pragma unroll
    for (int v = 0; v < 4; v++) av[v] = ldcs4((const float4*)Abase + v);

    for (int it = 0; it < NIT; it++) {
        const int buf = it & 1;

        {
            uint4 u0, u1;
            u0.x = f16x2(av[0].x, av[0].y); u0.y = f16x2(av[0].z, av[0].w);
            u0.z = f16x2(av[1].x, av[1].y); u0.w = f16x2(av[1].z, av[1].w);
            u1.x = f16x2(av[2].x, av[2].y); u1.y = f16x2(av[2].z, av[2].w);
            u1.z = f16x2(av[3].x, av[3].y); u1.w = f16x2(av[3].z, av[3].w);
            unsigned* d = &Ah[buf][arow * AW + ah * 8];
            *(uint4*)d = u0;
            *(uint4*)(d + 4) = u1;
        }
        if (it + 1 < NIT) {
            const float4* src = (const float4*)(Abase + (it + 1) * 32);
#pragma unroll
            for (int v = 0; v < 4; v++) av[v] = ldcs4(src + v);
        }
        __syncthreads();   // single barrier per iter (see R11 proof)

#pragma unroll
        for (int s = 0; s < 2; s++) {
            const uint2* Bk = Bg + (size_t)(it * 2 + s) * 512;
            uint32_t a[4][4];
#pragma unroll
            for (int mt = 0; mt < 4; mt++) {
                uint32_t sa = smem_u32(
                    &Ah[buf][(lm_row + mt * 16) * AW + s * 8 + lm_off]);
                ldmatrix4(a[mt], sa);
            }
            uint2 bv[4];
#pragma unroll
            for (int nf = 0; nf < 4; nf++)
                bv[nf] = __ldg(Bk + nf * 32);
#pragma unroll
            for (int mt = 0; mt < 4; mt++)
#pragma unroll
                for (int nf = 0; nf < 4; nf++)
                    mma16(acc[mt][nf], a[mt], bv[nf].x, bv[nf].y);
        }
    }

    const float b2s = b2[0];
    const int mmode = g_mask_mode;
#pragma unroll
    for (int mt = 0; mt < 4; mt++) {
        float p0 = 0.f, p1 = 0.f;
#pragma unroll
        for (int nf = 0; nf < 4; nf++) {
            const int cb = nw * 32 + nf * 8 + 2 * q;
            float w0 = W2[cb], w1 = W2[cb + 1];
            float v0 = b1[cb], v1 = b1[cb + 1];
            p0 += w0 * sigmoidf_fast(acc[mt][nf][0] + v0)
                + w1 * sigmoidf_fast(acc[mt][nf][1] + v1);
            p1 += w0 * sigmoidf_fast(acc[mt][nf][2] + v0)
                + w1 * sigmoidf_fast(acc[mt][nf][3] + v1);
        }
        p0 += __shfl_xor_sync(0xffffffffu, p0, 1);
        p0 += __shfl_xor_sync(0xffffffffu, p0, 2);
        p1 += __shfl_xor_sync(0xffffffffu, p1, 1);
        p1 += __shfl_xor_sync(0xffffffffu, p1, 2);
        if (q == 0) {
            int r = mw * 64 + mt * 16 + lr;
            part[nw][r]     = p0;
            part[nw][r + 8] = p1;
        }
    }
    __syncthreads();
    if (tid < TM) {
        size_t r = row_base + tid;
        float sc = part[0][tid] + part[1][tid] + part[2][tid] + part[3][tid] + b2s;
        g_scores[r] = read_mask(mask, r, mmode) ? neg_inf() : sc;
    }
}

// ============================================================================
// Hybrid bitonic sort (single array): 1024 elems, 512 threads.
// ============================================================================
__device__ __forceinline__ void bitonic1024_hybrid(float* s, int tid, bool desc)
{
    const unsigned FULL = 0xffffffffu;
    const int i0 = 2 * tid;

    float v0 = s[i0], v1 = s[i0 + 1];
#pragma unroll
    for (int k = 2; k <= 64; k <<= 1) {
#pragma unroll
        for (int j = 32; j >= 2; j >>= 1) {
            if (j < k) {
                const int d = j >> 1;
                float u0 = __shfl_xor_sync(FULL, v0, d);
                float u1 = __shfl_xor_sync(FULL, v1, d);
                bool up = ((i0 & k) == 0) == desc;
                bool lower = ((tid & d) == 0);
                bool keepmax = (up == lower);
                v0 = keepmax ? fmaxf(v0, u0) : fminf(v0, u0);
                v1 = keepmax ? fmaxf(v1, u1) : fminf(v1, u1);
            }
        }
        {
            bool up = ((i0 & k) == 0) == desc;
            float mx = fmaxf(v0, v1), mn = fminf(v0, v1);
            v0 = up ? mx : mn;
            v1 = up ? mn : mx;
        }
    }
    s[i0] = v0; s[i0 + 1] = v1;

#pragma unroll
    for (int k = 128; k <= 1024; k <<= 1) {
        for (int j = k >> 1; j >= 64; j >>= 1) {
            __syncthreads();
            int i = 2 * tid - (tid & (j - 1));
            int l = i + j;
            float a = s[i], c = s[l];
            bool up = ((i & k) == 0) == desc;
            if (up ? (a < c) : (a > c)) { s[i] = c; s[l] = a; }
        }
        __syncthreads();
        v0 = s[i0]; v1 = s[i0 + 1];
        {
            bool up = ((i0 & k) == 0) == desc;
#pragma unroll
            for (int j = 32; j >= 2; j >>= 1) {
                const int d = j >> 1;
                float u0 = __shfl_xor_sync(FULL, v0, d);
                float u1 = __shfl_xor_sync(FULL, v1, d);
                bool lower = ((tid & d) == 0);
                bool keepmax = (up == lower);
                v0 = keepmax ? fmaxf(v0, u0) : fminf(v0, u0);
                v1 = keepmax ? fmaxf(v1, u1) : fminf(v1, u1);
            }
            float mx = fmaxf(v0, v1), mn = fminf(v0, v1);
            v0 = up ? mx : mn;
            v1 = up ? mn : mx;
        }
        s[i0] = v0; s[i0 + 1] = v1;
    }
    __syncthreads();
}

// ============================================================================
// Kernel 2a: per-(slide,segment) sort of 1000 scores -> candidates
// ============================================================================
__global__ __launch_bounds__(512) void seg_topk_kernel()
{
    __shared__ float s[1024];
    __shared__ int s_cnt;
    const int blk = blockIdx.x;
    const int b = blk >> 3, seg = blk & 7;
    const int tid = threadIdx.x;
    const size_t base = (size_t)b * NN + seg * SEGLEN;

    if (tid == 0) s_cnt = 0;
    __syncthreads();
    int cnt = 0;
#pragma unroll 2
    for (int i = tid; i < 1024; i += 512) {
        float v = (i < SEGLEN) ? g_scores[base + i] : neg_inf();
        s[i] = v;
        if (v > -3.0e38f) cnt++;
    }
#pragma unroll
    for (int o = 16; o > 0; o >>= 1) cnt += __shfl_xor_sync(0xffffffffu, cnt, o);
    if ((tid & 31) == 0) atomicAdd(&s_cnt, cnt);
    __syncthreads();

    bitonic1024_hybrid(s, tid, true);   // descending

    const int valid = s_cnt;
    if (tid < NTOP) g_ctop[blk * NTOP + tid] = s[tid];
    if (tid >= 256 && tid < 256 + NBOT) {
        int t = tid - 256;
        int j = valid - 1 - t;
        g_cbot[blk * NBOT + t] = (j >= 0) ? s[j] : pos_inf();
    }
}

// ============================================================================
// Kernel 2b: 32 blocks — block (b, half): sort 800 candidates, write extreme.
// half 0 = top (desc), half 1 = bottom (asc). Top and bottom run CONCURRENTLY.
// ============================================================================
__global__ __launch_bounds__(512) void merge_kernel(float* __restrict__ out)
{
    __shared__ float c[1024];
    const int b = blockIdx.x >> 1;
    const int half = blockIdx.x & 1;
    const int tid = threadIdx.x;

    if (half == 0) {
#pragma unroll 2
        for (int i = tid; i < 1024; i += 512)
            c[i] = (i < SEGS * NTOP) ? g_ctop[b * SEGS * NTOP + i] : neg_inf();
        __syncthreads();
        bitonic1024_hybrid(c, tid, true);
        if (tid < NTOP) out[BB + b * NEXT + tid] = c[tid];
    } else {
#pragma unroll 2
        for (int i = tid; i < 1024; i += 512)
            c[i] = (i < SEGS * NBOT) ? g_cbot[b * SEGS * NBOT + i] : pos_inf();
        __syncthreads();
        bitonic1024_hybrid(c, tid, false);
        if (tid < NBOT) out[BB + b * NEXT + NTOP + tid] = c[tid];
    }
}

// ============================================================================
// Kernel 2c: tiny MLP 200 -> 128 -> 64 -> 1, reading extreme from out.
// ============================================================================
__global__ __launch_bounds__(128) void mlp_kernel(
    const float* __restrict__ Wm1, const float* __restrict__ bm1,
    const float* __restrict__ Wm2, const float* __restrict__ bm2,
    const float* __restrict__ Wm3, const float* __restrict__ bm3,
    float* __restrict__ out)
{
    __shared__ float ext[NEXT];
    __shared__ float g1[128];
    __shared__ float g2[64];
    const int b = blockIdx.x;
    const int tid = threadIdx.x;

    for (int i = tid; i < NEXT; i += 128) ext[i] = out[BB + b * NEXT + i];
    __syncthreads();

    {
        float a1 = bm1[tid];
        for (int i = 0; i < NEXT; i++) a1 += ext[i] * Wm1[i * 128 + tid];
        g1[tid] = sigmoidf_fast(a1);
    }
    __syncthreads();
    if (tid < 64) {
        float a2 = bm2[tid];
        for (int i = 0; i < 128; i++) a2 += g1[i] * Wm2[i * 64 + tid];
        g2[tid] = sigmoidf_fast(a2);
    }
    __syncthreads();
    if (tid == 0) {
        float y = bm3[0];
        for (int i = 0; i < 64; i++) y += g2[i] * Wm3[i];
        out[b] = y;
    }
}

extern "C" void kernel_launch(void* const* d_in, const int* in_sizes, int n_in,
                              void* d_out, int out_size)
{
    const float* F    = (const float*)d_in[0];
    const void*  mask = d_in[1];
    const float* W1   = (const float*)d_in[2];
    const float* b1   = (const float*)d_in[3];
    const float* W2   = (const float*)d_in[4];
    const float* b2   = (const float*)d_in[5];
    const float* Wm1  = (const float*)d_in[6];
    const float* bm1  = (const float*)d_in[7];
    const float* Wm2  = (const float*)d_in[8];
    const float* bm2  = (const float*)d_in[9];
    const float* Wm3  = (const float*)d_in[10];
    const float* bm3  = (const float*)d_in[11];
    float* out = (float*)d_out;

    prep_kernel<<<257, 256>>>(W1, (const unsigned*)mask);
    score_kernel<<<MROWS / TM, 256>>>(F, b1, W2, b2, mask);
    seg_topk_kernel<<<BB * SEGS, 512>>>();
    merge_kernel<<<BB * 2, 512>>>(out);
    mlp_kernel<<<BB, 128>>>(Wm1, bm1, Wm2, bm2, Wm3, bm3, out);
}

// round 17
// speedup vs baseline: 1.0051x; 1.0051x over previous
#include <cuda_runtime.h>
#include <cuda_fp16.h>
#include <cstdint>

// Problem constants (fixed shapes for Chowder_17188459119037)
#define BB     16
#define NN     8000
#define DD     2048
#define HH     128
#define MROWS  (BB * NN)        // 128000
#define NTOP   100
#define NBOT   100
#define NEXT   (NTOP + NBOT)    // 200

#define TM      128             // rows per CTA (R11 optimum)
#define NIT     (DD / 32)       // 64 k32 iterations
#define AW      20              // A smem row stride in uints (40 halfs)
#define SEGS    8
#define SEGLEN  (NN / SEGS)     // 1000

__device__ float g_scores[MROWS];
// W1 packed fp16 fragment order: [k16tile][ntile][lane] -> uint2
__device__ __align__(16) unsigned g_W1H[(DD / 16) * 16 * 32 * 2];
__device__ float g_ctop[BB * SEGS * NTOP];
__device__ float g_cbot[BB * SEGS * NBOT];
__device__ int   g_mask_mode;   // 0=int32, 1=uint8, 2=float32
__device__ int   g_done[BB];    // per-slide merge-completion counters

__device__ __forceinline__ float neg_inf() { return __int_as_float(0xff800000); }
__device__ __forceinline__ float pos_inf() { return __int_as_float(0x7f800000); }
__device__ __forceinline__ float sigmoidf_fast(float x) {
    return 1.0f / (1.0f + __expf(-x));
}
__device__ __forceinline__ bool read_mask(const void* mask, size_t r, int mode) {
    if (mode == 1) return ((const unsigned char*)mask)[r] != 0;
    if (mode == 0) return ((const int*)mask)[r] != 0;
    return ((const float*)mask)[r] != 0.0f;
}
__device__ __forceinline__ uint32_t smem_u32(const void* p) {
    uint32_t a;
    asm("{ .reg .u64 t; cvta.to.shared.u64 t, %1; cvt.u32.u64 %0, t; }"
        : "=r"(a) : "l"(p));
    return a;
}
__device__ __forceinline__ uint32_t f16x2(float lo, float hi) {
    uint32_t r;
    asm("cvt.rn.f16x2.f32 %0, %1, %2;" : "=r"(r) : "f"(hi), "f"(lo));
    return r;
}
// streaming (evict-first) float4 load — keeps A out of L1 LRU, protecting B
__device__ __forceinline__ float4 ldcs4(const float4* p) {
    float4 v;
    asm volatile("ld.global.cs.v4.f32 {%0,%1,%2,%3}, [%4];"
                 : "=f"(v.x), "=f"(v.y), "=f"(v.z), "=f"(v.w) : "l"(p));
    return v;
}
__device__ __forceinline__ void mma16(float* d, const uint32_t* a,
                                      uint32_t b0, uint32_t b1) {
    asm volatile(
        "mma.sync.aligned.m16n8k16.row.col.f32.f16.f16.f32 "
        "{%0,%1,%2,%3}, {%4,%5,%6,%7}, {%8,%9}, {%0,%1,%2,%3};"
        : "+f"(d[0]), "+f"(d[1]), "+f"(d[2]), "+f"(d[3])
        : "r"(a[0]), "r"(a[1]), "r"(a[2]), "r"(a[3]), "r"(b0), "r"(b1));
}
__device__ __forceinline__ void ldmatrix4(uint32_t* a, uint32_t saddr) {
    asm volatile(
        "ldmatrix.sync.aligned.m8n8.x4.shared.b16 {%0,%1,%2,%3}, [%4];"
        : "=r"(a[0]), "=r"(a[1]), "=r"(a[2]), "=r"(a[3]) : "r"(saddr));
}

// ============================================================================
// Kernel 0 (fused): blocks 0..255 pack W1; block 256 detects mask dtype and
// resets the per-slide merge counters (graph-replay safe).
// ============================================================================
__global__ void prep_kernel(const float* __restrict__ W1,
                            const unsigned* __restrict__ m) {
    if (blockIdx.x == 256) {
        __shared__ int s_f32, s_u8;
        if (threadIdx.x == 0) { s_f32 = 0; s_u8 = 0; }
        if (threadIdx.x < BB) g_done[threadIdx.x] = 0;
        __syncthreads();
        int f32 = 0, u8 = 0;
        for (int i = threadIdx.x; i < 8000; i += 256) {
            unsigned v = m[i];
            if (v == 0x3F800000u) f32 = 1;
            else if (v > 1u)      u8 = 1;
        }
        if (f32) s_f32 = 1;
        if (u8)  s_u8 = 1;
        __syncthreads();
        if (threadIdx.x == 0) g_mask_mode = s_f32 ? 2 : (s_u8 ? 1 : 0);
        return;
    }
    int i = blockIdx.x * 256 + threadIdx.x;   // 0..65535
    int lane = i & 31, nt = (i >> 5) & 15, tile = i >> 9;
    int n = nt * 8 + (lane >> 2);
    int k = tile * 16 + 2 * (lane & 3);
    uint32_t r0 = f16x2(W1[(size_t)k * HH + n],       W1[(size_t)(k + 1) * HH + n]);
    uint32_t r1 = f16x2(W1[(size_t)(k + 8) * HH + n], W1[(size_t)(k + 9) * HH + n]);
    ((uint2*)g_W1H)[i] = make_uint2(r0, r1);
}

// ============================================================================
// Kernel 1: fp16 mma GEMM (fp32 accum). CTA = 128x128, 256 thr, 2M x 4N.
// R15 configuration (L1-traffic optimum + streaming A loads). UNCHANGED.
// ============================================================================
__global__ __launch_bounds__(256, 2) void score_kernel(
    const float* __restrict__ F,
    const float* __restrict__ b1,
    const float* __restrict__ W2,
    const float* __restrict__ b2,
    const void*  __restrict__ mask)
{
    __shared__ unsigned Ah[2][TM * AW];    // 2 x 10 KB (fp16, stride 40 halfs)
    __shared__ float    part[4][TM];       // 2 KB

    const int tid  = threadIdx.x;
    const int lane = tid & 31;
    const int wid  = tid >> 5;
    const int nw   = wid & 3;     // 4 N-warps x 32 cols
    const int mw   = wid >> 2;    // 2 M-warps x 64 rows
    const int q    = lane & 3;
    const int lr   = lane >> 2;
    const size_t row_base = (size_t)blockIdx.x * TM;

    const int lm_row = mw * 64 + (lane & 15);
    const int lm_off = (lane >> 4) * 4;

    const int arow = tid >> 1;
    const int ah   = tid & 1;
    const float* Abase = F + (row_base + arow) * DD + ah * 16;

    const uint2* Bg = (const uint2*)g_W1H + (nw * 4) * 32 + lane;

    float acc[4][4][4];
#pragma unroll
    for (int mt = 0; mt < 4; mt++)
#pragma unroll
        for (int nf = 0; nf < 4; nf++)
#pragma unroll
            for (int e = 0; e < 4; e++) acc[mt][nf][e] = 0.f;

    float4 av[4];
#pragma unroll
    for (int v = 0; v < 4; v++) av[v] = ldcs4((const float4*)Abase + v);

    for (int it = 0; it < NIT; it++) {
        const int buf = it & 1;

        {
            uint4 u0, u1;
            u0.x = f16x2(av[0].x, av[0].y); u0.y = f16x2(av[0].z, av[0].w);
            u0.z = f16x2(av[1].x, av[1].y); u0.w = f16x2(av[1].z, av[1].w);
            u1.x = f16x2(av[2].x, av[2].y); u1.y = f16x2(av[2].z, av[2].w);
            u1.z = f16x2(av[3].x, av[3].y); u1.w = f16x2(av[3].z, av[3].w);
            unsigned* d = &Ah[buf][arow * AW + ah * 8];
            *(uint4*)d = u0;
            *(uint4*)(d + 4) = u1;
        }
        if (it + 1 < NIT) {
            const float4* src = (const float4*)(Abase + (it + 1) * 32);
#pragma unroll
            for (int v = 0; v < 4; v++) av[v] = ldcs4(src + v);
        }
        __syncthreads();   // single barrier per iter (see R11 proof)

#pragma unroll
        for (int s = 0; s < 2; s++) {
            const uint2* Bk = Bg + (size_t)(it * 2 + s) * 512;
            uint32_t a[4][4];
#pragma unroll
            for (int mt = 0; mt < 4; mt++) {
                uint32_t sa = smem_u32(
                    &Ah[buf][(lm_row + mt * 16) * AW + s * 8 + lm_off]);
                ldmatrix4(a[mt], sa);
            }
            uint2 bv[4];
#pragma unroll
            for (int nf = 0; nf < 4; nf++)
                bv[nf] = __ldg(Bk + nf * 32);
#pragma unroll
            for (int mt = 0; mt < 4; mt++)
#pragma unroll
                for (int nf = 0; nf < 4; nf++)
                    mma16(acc[mt][nf], a[mt], bv[nf].x, bv[nf].y);
        }
    }

    const float b2s = b2[0];
    const int mmode = g_mask_mode;
#pragma unroll
    for (int mt = 0; mt < 4; mt++) {
        float p0 = 0.f, p1 = 0.f;
#pragma unroll
        for (int nf = 0; nf < 4; nf++) {
            const int cb = nw * 32 + nf * 8 + 2 * q;
            float w0 = W2[cb], w1 = W2[cb + 1];
            float v0 = b1[cb], v1 = b1[cb + 1];
            p0 += w0 * sigmoidf_fast(acc[mt][nf][0] + v0)
                + w1 * sigmoidf_fast(acc[mt][nf][1] + v1);
            p1 += w0 * sigmoidf_fast(acc[mt][nf][2] + v0)
                + w1 * sigmoidf_fast(acc[mt][nf][3] + v1);
        }
        p0 += __shfl_xor_sync(0xffffffffu, p0, 1);
        p0 += __shfl_xor_sync(0xffffffffu, p0, 2);
        p1 += __shfl_xor_sync(0xffffffffu, p1, 1);
        p1 += __shfl_xor_sync(0xffffffffu, p1, 2);
        if (q == 0) {
            int r = mw * 64 + mt * 16 + lr;
            part[nw][r]     = p0;
            part[nw][r + 8] = p1;
        }
    }
    __syncthreads();
    if (tid < TM) {
        size_t r = row_base + tid;
        float sc = part[0][tid] + part[1][tid] + part[2][tid] + part[3][tid] + b2s;
        g_scores[r] = read_mask(mask, r, mmode) ? neg_inf() : sc;
    }
}

// ============================================================================
// Hybrid bitonic sort (single array): 1024 elems, 512 threads.
// ============================================================================
__device__ __forceinline__ void bitonic1024_hybrid(float* s, int tid, bool desc)
{
    const unsigned FULL = 0xffffffffu;
    const int i0 = 2 * tid;

    float v0 = s[i0], v1 = s[i0 + 1];
#pragma unroll
    for (int k = 2; k <= 64; k <<= 1) {
#pragma unroll
        for (int j = 32; j >= 2; j >>= 1) {
            if (j < k) {
                const int d = j >> 1;
                float u0 = __shfl_xor_sync(FULL, v0, d);
                float u1 = __shfl_xor_sync(FULL, v1, d);
                bool up = ((i0 & k) == 0) == desc;
                bool lower = ((tid & d) == 0);
                bool keepmax = (up == lower);
                v0 = keepmax ? fmaxf(v0, u0) : fminf(v0, u0);
                v1 = keepmax ? fmaxf(v1, u1) : fminf(v1, u1);
            }
        }
        {
            bool up = ((i0 & k) == 0) == desc;
            float mx = fmaxf(v0, v1), mn = fminf(v0, v1);
            v0 = up ? mx : mn;
            v1 = up ? mn : mx;
        }
    }
    s[i0] = v0; s[i0 + 1] = v1;

#pragma unroll
    for (int k = 128; k <= 1024; k <<= 1) {
        for (int j = k >> 1; j >= 64; j >>= 1) {
            __syncthreads();
            int i = 2 * tid - (tid & (j - 1));
            int l = i + j;
            float a = s[i], c = s[l];
            bool up = ((i & k) == 0) == desc;
            if (up ? (a < c) : (a > c)) { s[i] = c; s[l] = a; }
        }
        __syncthreads();
        v0 = s[i0]; v1 = s[i0 + 1];
        {
            bool up = ((i0 & k) == 0) == desc;
#pragma unroll
            for (int j = 32; j >= 2; j >>= 1) {
                const int d = j >> 1;
                float u0 = __shfl_xor_sync(FULL, v0, d);
                float u1 = __shfl_xor_sync(FULL, v1, d);
                bool lower = ((tid & d) == 0);
                bool keepmax = (up == lower);
                v0 = keepmax ? fmaxf(v0, u0) : fminf(v0, u0);
                v1 = keepmax ? fmaxf(v1, u1) : fminf(v1, u1);
            }
            float mx = fmaxf(v0, v1), mn = fminf(v0, v1);
            v0 = up ? mx : mn;
            v1 = up ? mn : mx;
        }
        s[i0] = v0; s[i0 + 1] = v1;
    }
    __syncthreads();
}

// ============================================================================
// Kernel 2a: per-(slide,segment) sort of 1000 scores -> candidates
// ============================================================================
__global__ __launch_bounds__(512) void seg_topk_kernel()
{
    __shared__ float s[1024];
    __shared__ int s_cnt;
    const int blk = blockIdx.x;
    const int b = blk >> 3, seg = blk & 7;
    const int tid = threadIdx.x;
    const size_t base = (size_t)b * NN + seg * SEGLEN;

    if (tid == 0) s_cnt = 0;
    __syncthreads();
    int cnt = 0;
#pragma unroll 2
    for (int i = tid; i < 1024; i += 512) {
        float v = (i < SEGLEN) ? g_scores[base + i] : neg_inf();
        s[i] = v;
        if (v > -3.0e38f) cnt++;
    }
#pragma unroll
    for (int o = 16; o > 0; o >>= 1) cnt += __shfl_xor_sync(0xffffffffu, cnt, o);
    if ((tid & 31) == 0) atomicAdd(&s_cnt, cnt);
    __syncthreads();

    bitonic1024_hybrid(s, tid, true);   // descending

    const int valid = s_cnt;
    if (tid < NTOP) g_ctop[blk * NTOP + tid] = s[tid];
    if (tid >= 256 && tid < 256 + NBOT) {
        int t = tid - 256;
        int j = valid - 1 - t;
        g_cbot[blk * NBOT + t] = (j >= 0) ? s[j] : pos_inf();
    }
}

// ============================================================================
// Kernel 2b: 32 blocks — block (b, half) sorts its 800 candidates and writes
// its half of the extreme values; the LAST of the two blocks per slide (via
// atomic counter + threadfence) then runs the tiny MLP. Deterministic: the
// MLP result is identical regardless of which block executes it.
// ============================================================================
__global__ __launch_bounds__(512) void merge_mlp_kernel(
    const float* __restrict__ Wm1, const float* __restrict__ bm1,
    const float* __restrict__ Wm2, const float* __restrict__ bm2,
    const float* __restrict__ Wm3, const float* __restrict__ bm3,
    float* __restrict__ out)
{
    __shared__ float c[1024];
    __shared__ float ext[NEXT];
    __shared__ float g1[128];
    __shared__ float g2[64];
    __shared__ int s_last;
    const int b = blockIdx.x >> 1;
    const int half = blockIdx.x & 1;
    const int tid = threadIdx.x;

    if (half == 0) {
#pragma unroll 2
        for (int i = tid; i < 1024; i += 512)
            c[i] = (i < SEGS * NTOP) ? g_ctop[b * SEGS * NTOP + i] : neg_inf();
        __syncthreads();
        bitonic1024_hybrid(c, tid, true);
        if (tid < NTOP) out[BB + b * NEXT + tid] = c[tid];
    } else {
#pragma unroll 2
        for (int i = tid; i < 1024; i += 512)
            c[i] = (i < SEGS * NBOT) ? g_cbot[b * SEGS * NBOT + i] : pos_inf();
        __syncthreads();
        bitonic1024_hybrid(c, tid, false);
        if (tid < NBOT) out[BB + b * NEXT + NTOP + tid] = c[tid];
    }

    // last-block-done: the second block per slide runs the MLP
    __threadfence();
    __syncthreads();
    if (tid == 0) s_last = (atomicAdd(&g_done[b], 1) == 1);
    __syncthreads();
    if (!s_last) return;
    __threadfence();   // acquire: peer's extreme writes now visible

    for (int i = tid; i < NEXT; i += 512) ext[i] = out[BB + b * NEXT + i];
    __syncthreads();

    if (tid < 128) {
        float a1 = bm1[tid];
        for (int i = 0; i < NEXT; i++) a1 += ext[i] * Wm1[i * 128 + tid];
        g1[tid] = sigmoidf_fast(a1);
    }
    __syncthreads();
    if (tid < 64) {
        float a2 = bm2[tid];
        for (int i = 0; i < 128; i++) a2 += g1[i] * Wm2[i * 64 + tid];
        g2[tid] = sigmoidf_fast(a2);
    }
    __syncthreads();
    if (tid == 0) {
        float y = bm3[0];
        for (int i = 0; i < 64; i++) y += g2[i] * Wm3[i];
        out[b] = y;
    }
}

extern "C" void kernel_launch(void* const* d_in, const int* in_sizes, int n_in,
                              void* d_out, int out_size)
{
    const float* F    = (const float*)d_in[0];
    const void*  mask = d_in[1];
    const float* W1   = (const float*)d_in[2];
    const float* b1   = (const float*)d_in[3];
    const float* W2   = (const float*)d_in[4];
    const float* b2   = (const float*)d_in[5];
    const float* Wm1  = (const float*)d_in[6];
    const float* bm1  = (const float*)d_in[7];
    const float* Wm2  = (const float*)d_in[8];
    const float* bm2  = (const float*)d_in[9];
    const float* Wm3  = (const float*)d_in[10];
    const float* bm3  = (const float*)d_in[11];
    float* out = (float*)d_out;

    prep_kernel<<<257, 256>>>(W1, (const unsigned*)mask);
    score_kernel<<<MROWS / TM, 256>>>(F, b1, W2, b2, mask);
    seg_topk_kernel<<<BB * SEGS, 512>>>();
    merge_mlp_kernel<<<BB * 2, 512>>>(Wm1, bm1, Wm2, bm2, Wm3, bm3, out);
}